// round 5
// baseline (speedup 1.0000x reference)
#include <cuda_runtime.h>
#include <cuda_bf16.h>
#include <math_constants.h>

#define N_NODES   50000
#define N_EDGES   1600000
#define IN_H      256
#define OUT_H     32
#define NHEAD     4
#define HDIM      128     // NHEAD*OUT_H
#define EDGE_H    64
#define N_ETYPES  8
#define NEG_SLOPE 0.2f

typedef unsigned long long ull;

// ---------------- scratch ---------------------------------------------------------
__device__ __align__(16) float  g_h[N_NODES * HDIM];     // projected node features
__device__ __align__(16) float  g_hl[N_NODES * NHEAD];
__device__ __align__(16) float  g_hr[N_NODES * NHEAD];
__device__ __align__(16) float  g_he[N_ETYPES * NHEAD];
__device__ __align__(16) float4 g_exps[N_EDGES];         // exp scores in CSR order
__device__ __align__(16) float  g_invf[N_NODES * NHEAD]; // 1/denom per node
__device__ int      g_counts[N_NODES + 1];
__device__ int      g_offsets[N_NODES + 1];
__device__ int      g_cursor[N_NODES];
__device__ int      g_ssorted[N_EDGES];                  // src in CSR order
__device__ unsigned g_maxhl, g_maxhr, g_maxhe;

// monotone float<->uint encoding for atomicMax over signed floats
__device__ __forceinline__ unsigned enc_f(float f) {
    unsigned u = __float_as_uint(f);
    return (u & 0x80000000u) ? ~u : (u | 0x80000000u);
}
__device__ __forceinline__ float dec_f(unsigned u) {
    return (u & 0x80000000u) ? __uint_as_float(u & 0x7FFFFFFFu)
                             : __uint_as_float(~u);
}

#define FMA2(d, a, b) asm("fma.rn.f32x2 %0, %1, %2, %0;" : "+l"(d) : "l"(a), "l"(b))
#define PACK2(p, v)   asm("mov.b64 %0, {%1, %2};" : "=l"(p) : "f"(v), "f"(v))
#define UNPACK2(lo, hi, p) asm("mov.b64 {%0, %1}, %2;" : "=f"(lo), "=f"(hi) : "l"(p))

// ---------------- K0: zero scratch ------------------------------------------------
__global__ void k_zero() {
    int i = blockIdx.x * blockDim.x + threadIdx.x;
    if (i <= N_NODES) g_counts[i] = 0;
    if (i == 0) { g_maxhl = 0u; g_maxhr = 0u; g_maxhe = 0u; }
}

// ---------------- K1: histogram of targets ---------------------------------------
__global__ void k_count(const int* __restrict__ edge) {
    int e = blockIdx.x * blockDim.x + threadIdx.x;
    if (e < N_EDGES) atomicAdd(&g_counts[edge[N_EDGES + e]], 1);
}

// ---------------- K2: h = nan_clean(x @ W) + fused hl/hr + maxes ------------------
__global__ __launch_bounds__(256, 2) void k_gemm(const float* __restrict__ x,
                                                 const float* __restrict__ W,
                                                 const float* __restrict__ a_l,
                                                 const float* __restrict__ a_r) {
    __shared__ ull   xs2[128][16];   // x value duplicated into both f32x2 lanes
    __shared__ float ws[16][128];
    const int t  = threadIdx.x;
    const int tx = t & 15;           // col group: cols tx*8 .. tx*8+7
    const int ty = t >> 4;           // 0..15: rows ty + 16*rr
    const int row0 = blockIdx.x * 128;

    ull acc[8][4];
#pragma unroll
    for (int r = 0; r < 8; r++)
#pragma unroll
        for (int c = 0; c < 4; c++) acc[r][c] = 0ull;

    for (int k0 = 0; k0 < IN_H; k0 += 16) {
#pragma unroll
        for (int i = 0; i < 2; i++) {              // 512 float4 x-loads
            int i4 = t + i * 256;
            int r = i4 >> 2, kk4 = i4 & 3;
            int row = row0 + r;
            float4 v = make_float4(0.f, 0.f, 0.f, 0.f);
            if (row < N_NODES)
                v = *(const float4*)(x + (size_t)row * IN_H + k0 + kk4 * 4);
            ull p0, p1, p2, p3;
            PACK2(p0, v.x); PACK2(p1, v.y); PACK2(p2, v.z); PACK2(p3, v.w);
            xs2[r][kk4 * 4 + 0] = p0;
            xs2[r][kk4 * 4 + 1] = p1;
            xs2[r][kk4 * 4 + 2] = p2;
            xs2[r][kk4 * 4 + 3] = p3;
        }
#pragma unroll
        for (int i = 0; i < 2; i++) {              // 512 float4 W-loads
            int i4 = t + i * 256;
            int kk = i4 >> 5, c4 = i4 & 31;
            *(float4*)&ws[kk][c4 * 4] = *(const float4*)(W + (size_t)(k0 + kk) * HDIM + c4 * 4);
        }
        __syncthreads();
#pragma unroll
        for (int kk = 0; kk < 16; kk++) {
            ull b0 = ((const ull*)&ws[kk][0])[tx * 4 + 0];
            ull b1 = ((const ull*)&ws[kk][0])[tx * 4 + 1];
            ull b2 = ((const ull*)&ws[kk][0])[tx * 4 + 2];
            ull b3 = ((const ull*)&ws[kk][0])[tx * 4 + 3];
#pragma unroll
            for (int rr = 0; rr < 8; rr++) {
                ull ax = xs2[ty + 16 * rr][kk];
                FMA2(acc[rr][0], ax, b0);
                FMA2(acc[rr][1], ax, b1);
                FMA2(acc[rr][2], ax, b2);
                FMA2(acc[rr][3], ax, b3);
            }
        }
        __syncthreads();
    }

    // ---- epilogue: store h + fused hl/hr ----
    const int hh  = tx >> 2;         // head of this thread's 8 cols
    const int sub = tx & 3;          // position within head (8 cols each)
    float al[8], ar[8];
    *(float4*)&al[0] = *(const float4*)(a_l + hh * OUT_H + sub * 8);
    *(float4*)&al[4] = *(const float4*)(a_l + hh * OUT_H + sub * 8 + 4);
    *(float4*)&ar[0] = *(const float4*)(a_r + hh * OUT_H + sub * 8);
    *(float4*)&ar[4] = *(const float4*)(a_r + hh * OUT_H + sub * 8 + 4);

    float ml = -CUDART_INF_F, mr = -CUDART_INF_F;
#pragma unroll
    for (int rr = 0; rr < 8; rr++) {
        int row = row0 + ty + 16 * rr;
        float v[8];
#pragma unroll
        for (int j = 0; j < 4; j++) UNPACK2(v[2 * j], v[2 * j + 1], acc[rr][j]);
#pragma unroll
        for (int j = 0; j < 8; j++) v[j] = (v[j] == v[j]) ? v[j] : 0.0f;
        float pl = 0.f, pr = 0.f;
        if (row < N_NODES) {
            *(float4*)(g_h + (size_t)row * HDIM + tx * 8)     = make_float4(v[0], v[1], v[2], v[3]);
            *(float4*)(g_h + (size_t)row * HDIM + tx * 8 + 4) = make_float4(v[4], v[5], v[6], v[7]);
#pragma unroll
            for (int j = 0; j < 8; j++) { pl += v[j] * al[j]; pr += v[j] * ar[j]; }
        }
        pl += __shfl_xor_sync(0xFFFFFFFFu, pl, 1);
        pl += __shfl_xor_sync(0xFFFFFFFFu, pl, 2);
        pr += __shfl_xor_sync(0xFFFFFFFFu, pr, 1);
        pr += __shfl_xor_sync(0xFFFFFFFFu, pr, 2);
        if (sub == 0 && row < N_NODES) {
            g_hl[row * NHEAD + hh] = pl;
            g_hr[row * NHEAD + hh] = pr;
            ml = fmaxf(ml, pl);
            mr = fmaxf(mr, pr);
        }
    }
#pragma unroll
    for (int o = 16; o > 0; o >>= 1) {
        ml = fmaxf(ml, __shfl_xor_sync(0xFFFFFFFFu, ml, o));
        mr = fmaxf(mr, __shfl_xor_sync(0xFFFFFFFFu, mr, o));
    }
    if ((t & 31) == 0) {
        if (ml > -CUDART_INF_F) atomicMax(&g_maxhl, enc_f(ml));
        if (mr > -CUDART_INF_F) atomicMax(&g_maxhr, enc_f(mr));
    }
}

// ---------------- K3: he[t,h] = (a_e * (edge_emb @ W_e)).sum(-1) + max ------------
// 32 blocks (type*4+head), 256 threads: (de, k-quarter). 16 MACs per thread.
__global__ void k_he(const float* __restrict__ edge_emb, const float* __restrict__ W_e,
                     const float* __restrict__ a_e) {
    __shared__ float emb[EDGE_H];
    __shared__ float part[256];
    int ti = blockIdx.x >> 2;
    int hh = blockIdx.x & 3;
    int t  = threadIdx.x;
    int de = t & 63;
    int kq = t >> 6;          // 0..3
    if (t < EDGE_H) emb[t] = edge_emb[ti * EDGE_H + t];
    __syncthreads();
    float p = 0.f;
#pragma unroll
    for (int k = kq * 16; k < kq * 16 + 16; k++)
        p += emb[k] * W_e[k * (EDGE_H * NHEAD) + hh * EDGE_H + de];
    part[t] = p;
    __syncthreads();
    if (t < 64) {
        float proj = part[t] + part[t + 64] + part[t + 128] + part[t + 192];
        float v = proj * a_e[hh * EDGE_H + t];
#pragma unroll
        for (int o = 16; o > 0; o >>= 1)
            v += __shfl_xor_sync(0xFFFFFFFFu, v, o);
        if ((t & 31) == 0) part[t >> 5] = v;
    }
    __syncthreads();
    if (t == 0) {
        float r = part[0] + part[1];
        g_he[ti * NHEAD + hh] = r;
        atomicMax(&g_maxhe, enc_f(r));
    }
}

// ---------------- K4: exclusive scan of counts -> offsets/cursor ------------------
__global__ void k_scan() {
    const int C = (N_NODES + 1023) / 1024;
    __shared__ int ssum[1024];
    int t = threadIdx.x;
    int beg = t * C;
    int end = min(beg + C, N_NODES);
    int local = 0;
#pragma unroll 8
    for (int i = beg; i < end; i++) local += g_counts[i];
    ssum[t] = local;
    __syncthreads();
    for (int d = 1; d < 1024; d <<= 1) {
        int v = (t >= d) ? ssum[t - d] : 0;
        __syncthreads();
        ssum[t] += v;
        __syncthreads();
    }
    int run = (t == 0) ? 0 : ssum[t - 1];
    for (int i = beg; i < end; i++) {
        g_offsets[i] = run;
        g_cursor[i]  = run;
        run += g_counts[i];
    }
    if (t == 1023) g_offsets[N_NODES] = ssum[1023];
}

// ---------------- K5: fused score + exp + CSR scatter + coalesced exp write -------
__global__ void k_edge(const int* __restrict__ edge, float* __restrict__ attn) {
    int e = blockIdx.x * blockDim.x + threadIdx.x;
    if (e >= N_EDGES) return;
    float M = dec_f(g_maxhl) + dec_f(g_maxhr) + dec_f(g_maxhe);
    int s  = edge[e];
    int tg = edge[N_EDGES + e];
    int ty = edge[2 * N_EDGES + e];
    float4 hl = *(const float4*)(g_hl + s * 4);
    float4 hr = *(const float4*)(g_hr + tg * 4);
    float4 he = *(const float4*)(g_he + ty * 4);
    float4 sc;
    sc.x = hl.x + hr.x + he.x;  sc.x = sc.x > 0.f ? sc.x : NEG_SLOPE * sc.x;
    sc.y = hl.y + hr.y + he.y;  sc.y = sc.y > 0.f ? sc.y : NEG_SLOPE * sc.y;
    sc.z = hl.z + hr.z + he.z;  sc.z = sc.z > 0.f ? sc.z : NEG_SLOPE * sc.z;
    sc.w = hl.w + hr.w + he.w;  sc.w = sc.w > 0.f ? sc.w : NEG_SLOPE * sc.w;
    float4 ex;
    ex.x = __expf(sc.x - M);
    ex.y = __expf(sc.y - M);
    ex.z = __expf(sc.z - M);
    ex.w = __expf(sc.w - M);
    *(float4*)(attn + (size_t)e * 4) = ex;           // coalesced, normalized later
    int pos = atomicAdd(&g_cursor[tg], 1);
    g_exps[pos]    = ex;
    g_ssorted[pos] = s;
}

// ---------------- K6: CSR aggregation, 2 warps per node (2 heads each) ------------
// software-pipelined (prefetch depth 1) to break the index->gather chain.
__global__ void k_agg(float* __restrict__ out) {
    int gw2  = (blockIdx.x * blockDim.x + threadIdx.x) >> 5;
    int lane = threadIdx.x & 31;
    int node = gw2 >> 1;
    int half = gw2 & 1;                 // heads 2*half, 2*half+1
    if (node >= N_NODES) return;
    int beg = g_offsets[node];
    int end = g_offsets[node + 1];

    const float2* exps2 = (const float2*)g_exps;
    float a0 = 0.f, a1 = 0.f, d0 = 0.f, d1 = 0.f;

    int    i   = beg;
    int    s_n = 0;
    float2 e_n = make_float2(0.f, 0.f);
    if (i < end) { s_n = g_ssorted[i]; e_n = exps2[2 * i + half]; }
    while (i < end) {
        int    s  = s_n;
        float2 ex = e_n;
        i++;
        if (i < end) { s_n = g_ssorted[i]; e_n = exps2[2 * i + half]; }
        const float* hp = g_h + (size_t)s * HDIM + half * 64 + lane;
        a0 += ex.x * hp[0];
        a1 += ex.y * hp[32];
        d0 += ex.x;
        d1 += ex.y;
    }
    float i0 = 1.0f / (d0 + 1e-16f);
    float i1 = 1.0f / (d1 + 1e-16f);
    float* op = out + (size_t)node * HDIM + half * 64 + lane;
    op[0]  = a0 * i0;
    op[32] = a1 * i1;
    if (lane == 0)
        *(float2*)(g_invf + node * 4 + half * 2) = make_float2(i0, i1);
}

// ---------------- K7: attn finalize: attn[e] = exp[e] * inv[trg[e]] (coalesced) ---
__global__ void k_attn(const int* __restrict__ edge, float* __restrict__ attn) {
    int e = blockIdx.x * blockDim.x + threadIdx.x;
    if (e >= N_EDGES) return;
    int tg = edge[N_EDGES + e];
    float4 ex  = *(const float4*)(attn + (size_t)e * 4);
    float4 inv = *(const float4*)(g_invf + tg * 4);
    ex.x *= inv.x; ex.y *= inv.y; ex.z *= inv.z; ex.w *= inv.w;
    *(float4*)(attn + (size_t)e * 4) = ex;
}

// ---------------- launch ----------------------------------------------------------
extern "C" void kernel_launch(void* const* d_in, const int* in_sizes, int n_in,
                              void* d_out, int out_size) {
    const int*   edge     = (const int*)d_in[0];
    const float* x        = (const float*)d_in[1];
    const float* edge_emb = (const float*)d_in[2];
    const float* W        = (const float*)d_in[3];
    const float* W_e      = (const float*)d_in[4];
    const float* a_l      = (const float*)d_in[5];
    const float* a_r      = (const float*)d_in[6];
    const float* a_e      = (const float*)d_in[7];
    float* out  = (float*)d_out;
    float* attn = out + (size_t)N_NODES * HDIM;

    (void)in_sizes; (void)n_in; (void)out_size;

    k_zero <<<(N_NODES + 256) / 256, 256>>>();
    k_count<<<N_EDGES / 256, 256>>>(edge);
    k_gemm <<<(N_NODES + 127) / 128, 256>>>(x, W, a_l, a_r);
    k_he   <<<N_ETYPES * NHEAD, 256>>>(edge_emb, W_e, a_e);
    k_scan <<<1, 1024>>>();
    k_edge <<<N_EDGES / 256, 256>>>(edge, attn);
    k_agg  <<<(N_NODES * 2 * 32 + 255) / 256, 256>>>(out);
    k_attn <<<N_EDGES / 256, 256>>>(edge, attn);
}